// round 9
// baseline (speedup 1.0000x reference)
#include <cuda_runtime.h>

#define T_MAX   16384
#define P_MAX   (T_MAX / 2)
#define NN      97
#define IN_T    12
#define HID     6
#define CH_L    128
#define CH_W    64

typedef unsigned long long u64;

// ----------------------------------------------------------------------------
// Scratch (__device__ globals)
// ----------------------------------------------------------------------------
__device__ float2 g_alp[(size_t)P_MAX * NN * HID];    // LSTM out, packed pairs [p][n][h]{t0,t1}
__device__ float2 g_f3p[(size_t)P_MAX * NN * HID];    // conv3 out, packed pairs
__device__ float4 g_wt1[NN * 194];                    // [ci][co] -> {kh0,kh1,kh2,0}
__device__ float4 g_wt2[194 * 194];
__device__ float4 g_wt3[194 * NN];
__device__ float2 g_bnp[(size_t)(P_MAX / 4 + 1) * NN];// per-block bn partials (sum,sumsq)
__device__ float  g_mean[NN];
__device__ float  g_rstd[NN];

// ----------------------------------------------------------------------------
// helpers
// ----------------------------------------------------------------------------
__device__ __forceinline__ float ex2_f(float x) {
    float r; asm("ex2.approx.ftz.f32 %0, %1;" : "=f"(r) : "f"(x)); return r;
}
__device__ __forceinline__ float rcp_f(float x) {
    float r; asm("rcp.approx.ftz.f32 %0, %1;" : "=f"(r) : "f"(x)); return r;
}
__device__ __forceinline__ float tanh_f(float x) {
    return fmaf(-2.0f, rcp_f(1.0f + ex2_f(x * 2.885390082f)), 1.0f);
}
__device__ __forceinline__ u64 pk2(float lo, float hi) {
    u64 r; asm("mov.b64 %0, {%1, %2};" : "=l"(r) : "f"(lo), "f"(hi)); return r;
}
__device__ __forceinline__ void upk2(float& lo, float& hi, u64 v) {
    asm("mov.b64 {%0, %1}, %2;" : "=f"(lo), "=f"(hi) : "l"(v));
}
__device__ __forceinline__ void fma2(u64& d, u64 a, u64 b) {
    asm("fma.rn.f32x2 %0, %1, %2, %3;" : "=l"(d) : "l"(a), "l"(b), "l"(d));
}
__device__ __forceinline__ u64 add2(u64 a, u64 b) {
    u64 d; asm("add.rn.f32x2 %0, %1, %2;" : "=l"(d) : "l"(a), "l"(b)); return d;
}

// ----------------------------------------------------------------------------
// K0: conv weight repack (only kw==1 of 3x3 touches data; W=1, pad 1)
// ----------------------------------------------------------------------------
template <int STAGE>
__global__ void k_prep_weights(const float* __restrict__ w) {
    constexpr int CIN  = (STAGE == 1) ? NN  : 194;
    constexpr int COUT = (STAGE == 3) ? NN  : 194;
    float4* wp = (STAGE == 1) ? g_wt1 : (STAGE == 2) ? g_wt2 : g_wt3;
    int idx = blockIdx.x * blockDim.x + threadIdx.x;
    if (idx >= CIN * COUT) return;
    int co = idx % COUT, ci = idx / COUT;
    float4 v;
    v.x = w[((co * CIN + ci) * 3 + 0) * 3 + 1];
    v.y = w[((co * CIN + ci) * 3 + 1) * 3 + 1];
    v.z = w[((co * CIN + ci) * 3 + 2) * 3 + 1];
    v.w = 0.0f;
    wp[ci * COUT + co] = v;
}

// ----------------------------------------------------------------------------
// K1: fused xproj + chunk-parallel LSTM, ONE NODE PER LANE.
// Each lane owns a full node: h[6], c[6] in registers; all 24 gate rows'
// weights are broadcast LDS.128 reads from smem (conflict-free, N=1).
// No shuffles at all. Warm-start CH_W steps early (truncation ~1e-7 worst).
// Math sequence identical to previous rounds (bias, x-FMAs asc, h-FMAs asc,
// EX2/RCP activations) -> bitwise-same trajectory.
// smem row layout (20 floats): [wih 0..11 | whh 0..5 | bias | pad3]
// ----------------------------------------------------------------------------
__global__ void __launch_bounds__(128) k_lstm_lane(
        const float* __restrict__ X, const float* __restrict__ Wih,
        const float* __restrict__ bih, const float* __restrict__ bhh,
        const float* __restrict__ Whh, int T) {
    __shared__ __align__(16) float sw[24 * 20];

    int tid = threadIdx.x;
    for (int i = tid; i < 24 * 20; i += 128) {
        int r = i / 20, cc = i % 20;
        float v = 0.0f;
        if (cc < 12)      v = __ldg(Wih + r * IN_T + cc);
        else if (cc < 18) v = __ldg(Whh + r * 6 + (cc - 12));
        else if (cc == 18) v = __ldg(bih + r) + __ldg(bhh + r);
        sw[i] = v;
    }
    __syncthreads();

    int n  = (tid < NN) ? tid : NN - 1;
    bool wr = (tid < NN);

    int tout = blockIdx.x * CH_L;
    int s = tout - CH_W; if (s < 0) s = 0;
    int e = tout + CH_L; if (e > T) e = T;

    float h[6], c[6];
#pragma unroll
    for (int k = 0; k < 6; k++) { h[k] = 0.0f; c[k] = 0.0f; }

    const float4* xr = (const float4*)X;
    size_t xb = (size_t)(s * NN + n) * 3;
    float4 A0 = __ldg(xr + xb), B0 = __ldg(xr + xb + 1), C0 = __ldg(xr + xb + 2);

    float* alp = (float*)g_alp;

    for (int t = s; t < e; t++) {
        float x[12] = {A0.x, A0.y, A0.z, A0.w, B0.x, B0.y, B0.z, B0.w,
                       C0.x, C0.y, C0.z, C0.w};
        int tn = (t + 1 < e) ? t + 1 : t;
        size_t nb = (size_t)(tn * NN + n) * 3;
        A0 = __ldg(xr + nb); B0 = __ldg(xr + nb + 1); C0 = __ldg(xr + nb + 2);

        float acts[24];
#pragma unroll
        for (int r = 0; r < 24; r++) {
            const float4* w4 = (const float4*)(sw + r * 20);
            float4 wA = w4[0], wB = w4[1], wC = w4[2], wD = w4[3], wE = w4[4];
            // gate = (bih+bhh) + sum_f x[f]*wih[f] + sum_k h[k]*whh[k]
            float acc = wE.z;
            acc = fmaf(x[0],  wA.x, acc); acc = fmaf(x[1],  wA.y, acc);
            acc = fmaf(x[2],  wA.z, acc); acc = fmaf(x[3],  wA.w, acc);
            acc = fmaf(x[4],  wB.x, acc); acc = fmaf(x[5],  wB.y, acc);
            acc = fmaf(x[6],  wB.z, acc); acc = fmaf(x[7],  wB.w, acc);
            acc = fmaf(x[8],  wC.x, acc); acc = fmaf(x[9],  wC.y, acc);
            acc = fmaf(x[10], wC.z, acc); acc = fmaf(x[11], wC.w, acc);
            acc = fmaf(h[0], wD.x, acc); acc = fmaf(h[1], wD.y, acc);
            acc = fmaf(h[2], wD.z, acc); acc = fmaf(h[3], wD.w, acc);
            acc = fmaf(h[4], wE.x, acc); acc = fmaf(h[5], wE.y, acc);

            bool isg = (r >= 12) && (r < 18);
            float AeL = isg ? -2.885390082f : -1.442695041f;
            float Bc  = isg ?  2.0f : 1.0f;
            float Cc  = isg ? -1.0f : 0.0f;
            float rr  = rcp_f(1.0f + ex2_f(acc * AeL));
            acts[r] = fmaf(Bc, rr, Cc);
        }

#pragma unroll
        for (int jj = 0; jj < 6; jj++) {
            c[jj] = fmaf(acts[6 + jj], c[jj], acts[jj] * acts[12 + jj]);
            h[jj] = tanh_f(acts[18 + jj] * tanh_f(c[jj]));
        }

        if (t >= tout && wr) {
            size_t ob = (((size_t)(t >> 1) * NN + n) * 6) * 2 + (t & 1);
#pragma unroll
            for (int jj = 0; jj < 6; jj++) alp[ob + 2 * jj] = h[jj];
        }
    }
}

// ----------------------------------------------------------------------------
// conv accumulation core: 16 FFMA2 per (ci, pair); broadcast smem reads
// ----------------------------------------------------------------------------
template <int CIN>
__device__ __forceinline__ void conv_accum(const float2* __restrict__ xin,
                                           const float4* __restrict__ w4,
                                           int COUT, int co, int cbeg, int cend,
                                           u64 acc[4][6]) {
#pragma unroll 2
    for (int ci = cbeg; ci < cend; ci++) {
        float4 w = __ldg(w4 + ci * COUT + co);
        u64 wx = pk2(w.x, w.x), wy = pk2(w.y, w.y), wz = pk2(w.z, w.z);
#pragma unroll
        for (int pr = 0; pr < 4; pr++) {
            const ulonglong2* vp = (const ulonglong2*)(xin + ((size_t)pr * CIN + ci) * 6);
            ulonglong2 qa = vp[0], qb = vp[1], qc = vp[2];
            u64 v1 = qa.x, v2 = qa.y, v3 = qb.x, v4 = qb.y, v5 = qc.x, v6 = qc.y;
            fma2(acc[pr][0], wy, v1); fma2(acc[pr][0], wz, v2);
            fma2(acc[pr][1], wx, v1); fma2(acc[pr][1], wy, v2); fma2(acc[pr][1], wz, v3);
            fma2(acc[pr][2], wx, v2); fma2(acc[pr][2], wy, v3); fma2(acc[pr][2], wz, v4);
            fma2(acc[pr][3], wx, v3); fma2(acc[pr][3], wy, v4); fma2(acc[pr][3], wz, v5);
            fma2(acc[pr][4], wx, v4); fma2(acc[pr][4], wy, v5); fma2(acc[pr][4], wz, v6);
            fma2(acc[pr][5], wx, v5); fma2(acc[pr][5], wy, v6);
        }
    }
}

// ----------------------------------------------------------------------------
// K2: FUSED conv1->conv2->conv3 (+relu) for 4 packed pairs per block.
// Aliased smem (74496 B -> up to 3 blocks/SM):
//   A [0,18624)        : input (stage1 reads), then stage2 output co<97
//   B [18624,55872)    : stage1 output (194 ch)
//   C [55872,74496)    : stage2 output co>=97
// Stage 3 split-K: even lanes read A (ci 0..96), odd lanes read C (ci 97..193).
// Also emits per-block BatchNorm partials from registers.
// ----------------------------------------------------------------------------
__global__ void __launch_bounds__(224) k_conv_fused(
        const float* __restrict__ bc1, const float* __restrict__ bc2,
        const float* __restrict__ bc3, int P) {
    extern __shared__ __align__(16) char smem_raw[];
    float2* sA = (float2*)smem_raw;                       // [4][97][6]
    float2* sB = (float2*)(smem_raw + 18624);             // [4][194][6]
    float2* sC = (float2*)(smem_raw + 55872);             // [4][97][6]

    int p0  = blockIdx.x * 4;
    int tid = threadIdx.x;
    int pv  = P - p0; if (pv > 4) pv = 4;

    // stage inputs into A: flat vector copy
    {
        const int NV = 4 * NN * 3;
        ulonglong2*       sd = (ulonglong2*)sA;
        const ulonglong2* sg = (const ulonglong2*)g_alp + (size_t)p0 * NN * 3;
        if (pv == 4) {
            for (int i = tid; i < NV; i += 224) sd[i] = __ldg(sg + i);
        } else {
            int pvv = pv * NN * 3;
            for (int i = tid; i < NV; i += 224) {
                ulonglong2 z; z.x = 0ull; z.y = 0ull;
                sd[i] = (i < pvv) ? __ldg(sg + i) : z;
            }
        }
    }
    __syncthreads();

    u64 acc[4][6];

    // ---- stage 1: 97 -> 194  (reads A, writes B) ----
    {
        int co = (tid < 194) ? tid : 193;
        float b = __ldg(bc1 + co);
        u64 bb = pk2(b, b);
#pragma unroll
        for (int pr = 0; pr < 4; pr++)
#pragma unroll
            for (int hh = 0; hh < 6; hh++) acc[pr][hh] = bb;
        conv_accum<NN>(sA, g_wt1, 194, co, 0, NN, acc);
        if (tid < 194) {
#pragma unroll
            for (int pr = 0; pr < 4; pr++) {
                u64 r[6];
#pragma unroll
                for (int hh = 0; hh < 6; hh++) {
                    float lo, hi; upk2(lo, hi, acc[pr][hh]);
                    r[hh] = pk2(fmaxf(lo, 0.0f), fmaxf(hi, 0.0f));
                }
                ulonglong2* dst = (ulonglong2*)(sB + ((size_t)pr * 194 + co) * 6);
                ulonglong2 q0, q1, q2;
                q0.x = r[0]; q0.y = r[1]; q1.x = r[2]; q1.y = r[3]; q2.x = r[4]; q2.y = r[5];
                dst[0] = q0; dst[1] = q1; dst[2] = q2;
            }
        }
    }
    __syncthreads();

    // ---- stage 2: 194 -> 194 (reads B, writes A[co<97] / C[co>=97]) ----
    {
        int co = (tid < 194) ? tid : 193;
        float b = __ldg(bc2 + co);
        u64 bb = pk2(b, b);
#pragma unroll
        for (int pr = 0; pr < 4; pr++)
#pragma unroll
            for (int hh = 0; hh < 6; hh++) acc[pr][hh] = bb;
        conv_accum<194>(sB, g_wt2, 194, co, 0, 194, acc);
        if (tid < 194) {
            float2* reg = (co < NN) ? sA : sC;
            int col = (co < NN) ? co : co - NN;
#pragma unroll
            for (int pr = 0; pr < 4; pr++) {
                u64 r[6];
#pragma unroll
                for (int hh = 0; hh < 6; hh++) {
                    float lo, hi; upk2(lo, hi, acc[pr][hh]);
                    r[hh] = pk2(fmaxf(lo, 0.0f), fmaxf(hi, 0.0f));
                }
                ulonglong2* dst = (ulonglong2*)(reg + ((size_t)pr * NN + col) * 6);
                ulonglong2 q0, q1, q2;
                q0.x = r[0]; q0.y = r[1]; q1.x = r[2]; q1.y = r[3]; q2.x = r[4]; q2.y = r[5];
                dst[0] = q0; dst[1] = q1; dst[2] = q2;
            }
        }
    }
    __syncthreads();

    // ---- stage 3: 194 -> 97, split-K: gg=0 reads A (ci 0..96), gg=1 reads C ----
    {
        int gg = tid & 1;
        int co = tid >> 1; if (co > NN - 1) co = NN - 1;
        const float2* reg = gg ? sC : sA;
        float b = __ldg(bc3 + co);
        u64 binit = (gg == 0) ? pk2(b, b) : 0ull;
#pragma unroll
        for (int pr = 0; pr < 4; pr++)
#pragma unroll
            for (int hh = 0; hh < 6; hh++) acc[pr][hh] = binit;
        conv_accum<NN>(reg, g_wt3 + (size_t)gg * NN * NN, NN, co, 0, NN, acc);

#pragma unroll
        for (int pr = 0; pr < 4; pr++)
#pragma unroll
            for (int hh = 0; hh < 6; hh++) {
                u64 o = __shfl_down_sync(0xffffffffu, acc[pr][hh], 1);
                acc[pr][hh] = add2(acc[pr][hh], o);
            }

        if ((tid & 1) == 0 && tid < 2 * NN) {
            float s = 0.0f, s2 = 0.0f;
#pragma unroll
            for (int pr = 0; pr < 4; pr++) {
                if (pr < pv) {
                    u64 r[6];
#pragma unroll
                    for (int hh = 0; hh < 6; hh++) {
                        float lo, hi; upk2(lo, hi, acc[pr][hh]);
                        lo = fmaxf(lo, 0.0f); hi = fmaxf(hi, 0.0f);
                        s += lo + hi;
                        s2 = fmaf(lo, lo, s2);
                        s2 = fmaf(hi, hi, s2);
                        r[hh] = pk2(lo, hi);
                    }
                    ulonglong2* yo = (ulonglong2*)g_f3p + ((size_t)(p0 + pr) * NN + co) * 3;
                    ulonglong2 q0, q1, q2;
                    q0.x = r[0]; q0.y = r[1]; q1.x = r[2]; q1.y = r[3]; q2.x = r[4]; q2.y = r[5];
                    yo[0] = q0; yo[1] = q1; yo[2] = q2;
                }
            }
            g_bnp[(size_t)blockIdx.x * NN + co] = make_float2(s, s2);
        }
    }
}

// ----------------------------------------------------------------------------
// K3: reduce per-block bn partials -> mean/rstd per channel
// ----------------------------------------------------------------------------
__global__ void k_bn_final(int T, int nblk) {
    int ch = blockIdx.x;
    float s = 0.0f, s2 = 0.0f;
    for (int b = threadIdx.x; b < nblk; b += 256) {
        float2 p = g_bnp[(size_t)b * NN + ch];
        s += p.x; s2 += p.y;
    }
    __shared__ float sh[256], sh2[256];
    sh[threadIdx.x] = s; sh2[threadIdx.x] = s2;
    __syncthreads();
    for (int o = 128; o > 0; o >>= 1) {
        if (threadIdx.x < o) {
            sh[threadIdx.x]  += sh[threadIdx.x + o];
            sh2[threadIdx.x] += sh2[threadIdx.x + o];
        }
        __syncthreads();
    }
    if (threadIdx.x == 0) {
        float Nf  = (float)T * (float)HID;
        float m   = sh[0] / Nf;
        float var = sh2[0] / Nf - m * m;
        g_mean[ch] = m;
        g_rstd[ch] = rsqrtf(var + 1e-5f);
    }
}

// ----------------------------------------------------------------------------
// K4: BN affine + Linear(6,6) epilogue; one thread per (pair, node).
// ----------------------------------------------------------------------------
__global__ void k_finalize(const float* __restrict__ gamma, const float* __restrict__ beta,
                           const float* __restrict__ Wl, const float* __restrict__ bl,
                           float* __restrict__ out, int P) {
    int idx = blockIdx.x * blockDim.x + threadIdx.x;
    if (idx >= P * NN) return;
    int n = idx % NN;
    int p = idx / NN;
    float m = g_mean[n], r = g_rstd[n];
    float ga = __ldg(gamma + n), be = __ldg(beta + n);

    const float4* f = (const float4*)g_f3p + (size_t)idx * 3;
    float4 A = __ldg(f), B = __ldg(f + 1), C = __ldg(f + 2);
    float ft[12] = {A.x, A.y, A.z, A.w, B.x, B.y, B.z, B.w, C.x, C.y, C.z, C.w};

#pragma unroll
    for (int tt = 0; tt < 2; tt++) {
        float v[6];
#pragma unroll
        for (int h = 0; h < 6; h++) v[h] = fmaf((ft[2 * h + tt] - m) * r, ga, be);
        float* op = out + ((size_t)(2 * p + tt) * NN + n) * 6;
#pragma unroll
        for (int jj = 0; jj < 6; jj++) {
            float acc = __ldg(bl + jj);
#pragma unroll
            for (int k = 0; k < 6; k++) acc = fmaf(v[k], __ldg(Wl + jj * 6 + k), acc);
            op[jj] = acc;
        }
    }
}

// ----------------------------------------------------------------------------
// Launch. Inputs: 0 A_hat(unused) 1 X 2 V_asist(unused) 3 W_ih 4 W_hh 5 b_ih
// 6 b_hh 7 Wc1 8 bc1 9 Wc2 10 bc2 11 Wc3 12 bc3 13 gamma 14 beta 15 Wl 16 bl
// ----------------------------------------------------------------------------
extern "C" void kernel_launch(void* const* d_in, const int* in_sizes, int n_in,
                              void* d_out, int out_size) {
    const float* X     = (const float*)d_in[1];
    const float* Wih   = (const float*)d_in[3];
    const float* Whh   = (const float*)d_in[4];
    const float* bih   = (const float*)d_in[5];
    const float* bhh   = (const float*)d_in[6];
    const float* Wc1   = (const float*)d_in[7];
    const float* bc1   = (const float*)d_in[8];
    const float* Wc2   = (const float*)d_in[9];
    const float* bc2   = (const float*)d_in[10];
    const float* Wc3   = (const float*)d_in[11];
    const float* bc3   = (const float*)d_in[12];
    const float* gamma = (const float*)d_in[13];
    const float* beta  = (const float*)d_in[14];
    const float* Wl    = (const float*)d_in[15];
    const float* bl    = (const float*)d_in[16];
    float* out = (float*)d_out;

    int T = in_sizes[1] / (NN * IN_T);   // 16384
    if (T > T_MAX) T = T_MAX;
    int P = T / 2;

    const int SMEM_FUSED = 74496;
    cudaFuncSetAttribute(k_conv_fused, cudaFuncAttributeMaxDynamicSharedMemorySize,
                         SMEM_FUSED);

    k_prep_weights<1><<<(NN * 194 + 255) / 256, 256>>>(Wc1);
    k_prep_weights<2><<<(194 * 194 + 255) / 256, 256>>>(Wc2);
    k_prep_weights<3><<<(194 * NN + 255) / 256, 256>>>(Wc3);

    int nch = (T + CH_L - 1) / CH_L;
    k_lstm_lane<<<nch, 128>>>(X, Wih, bih, bhh, Whh, T);

    int nblk = (P + 3) / 4;
    k_conv_fused<<<nblk, 224, SMEM_FUSED>>>(bc1, bc2, bc3, P);

    k_bn_final<<<NN, 256>>>(T, nblk);

    {
        int total = P * NN;
        k_finalize<<<(total + 255) / 256, 256>>>(gamma, beta, Wl, bl, out, P);
    }
}